// round 8
// baseline (speedup 1.0000x reference)
#include <cuda_runtime.h>
#include <cstdint>

// out = relu( GroupNorm32( Wv @ feat + bv, gn_v_g, gn_v_b ) )
// (softmax-weighted sum in the reference is identity: v is constant along the
//  softmax axis and softmax rows sum to 1).
//
// feat [2,128,512], Wv [128,128], out [2,128,512].
// Grid: 128 blocks = 64 clusters of 2 (cluster = two point-slices of one GN
// group).  512 threads/block = 16 warps = 4 warps/SMSP.
// Thread: tx = 64 float4 columns, ty = 8 cc-eighths (16 cc each);
// 16 LDG.128 issued up-front (MLP=16) + 256 FMA-inst.
// cc-partials folded 8->4->2->regs in smem (3 syncs); cross-slice GN stats
// exchanged via mapa + st.shared::cluster + barrier.cluster (deterministic,
// graph-replay safe, no global state).

#define C_CH     128
#define NPT      512
#define CH_PER_G 4
#define EPS_GN   1e-5f
#define NTHREADS 512
#define ROW4     (NPT / 4)     // 128 float4 per feat row
#define CC_PER_T (C_CH / 8)    // 16 cc per ty

__device__ __forceinline__ uint32_t smem_u32(const void* p) {
    uint32_t a;
    asm("{ .reg .u64 t; cvta.to.shared.u64 t, %1; cvt.u32.u64 %0, t; }"
        : "=r"(a) : "l"(p));
    return a;
}

__device__ __forceinline__ float4 f4add(float4 a, float4 b) {
    a.x += b.x; a.y += b.y; a.z += b.z; a.w += b.w; return a;
}

__global__ __launch_bounds__(NTHREADS, 1) __cluster_dims__(2, 1, 1)
void fused_v_gn_relu_kernel(const float* __restrict__ feat,
                            const float* __restrict__ Wv,
                            const float* __restrict__ bv,
                            const float* __restrict__ gamma,
                            const float* __restrict__ beta,
                            float* __restrict__ out) {
    const int x    = blockIdx.x;
    const int s    = x & 1;          // slice (== cluster rank)
    const int pair = x >> 1;
    const int g    = pair & 31;      // group 0..31
    const int b    = pair >> 5;      // batch 0..1
    const int c0   = g * CH_PER_G;
    const int t    = threadIdx.x;    // 0..511
    const int tx   = t & 63;         // float4 column within slice
    const int ty   = t >> 6;         // cc eighth (0..7)

    __shared__ float  wt_s[C_CH * CH_PER_G];        // transposed Wv, 2KB
    __shared__ float4 part_s[8 * CH_PER_G * 64];    // [ty][c][col], 32KB
    __shared__ float  red_s[2 * 8];
    __shared__ float  xch[2][2];                    // [slice][{sum,sumsq}]

    // Issue all 16 feat loads first (cold-start latency overlaps Wv staging).
    const float4* fp = (const float4*)(feat + (size_t)b * C_CH * NPT)
                       + (size_t)(ty * CC_PER_T) * ROW4 + s * 64 + tx;
    float4 f[CC_PER_T];
    #pragma unroll
    for (int i = 0; i < CC_PER_T; i++) f[i] = fp[i * ROW4];

    // Stage Wv transposed: wt_s[cc*4 + c] = Wv[(c0+c)*128 + cc]; 1 elem/thread.
    wt_s[t] = Wv[(c0 + (t & 3)) * C_CH + (t >> 2)];
    __syncthreads();

    const float4* wt4 = (const float4*)wt_s;
    const int wbase = ty * CC_PER_T;

    float4 acc[CH_PER_G];
    #pragma unroll
    for (int c = 0; c < CH_PER_G; c++) {
        const float bvc = (ty == 0) ? bv[c0 + c] : 0.f;
        acc[c].x = bvc; acc[c].y = bvc; acc[c].z = bvc; acc[c].w = bvc;
    }

    #pragma unroll
    for (int i = 0; i < CC_PER_T; i++) {
        const float4 w = wt4[wbase + i];   // broadcast LDS.128
        const float4 v = f[i];
        acc[0].x = fmaf(w.x, v.x, acc[0].x);
        acc[0].y = fmaf(w.x, v.y, acc[0].y);
        acc[0].z = fmaf(w.x, v.z, acc[0].z);
        acc[0].w = fmaf(w.x, v.w, acc[0].w);
        acc[1].x = fmaf(w.y, v.x, acc[1].x);
        acc[1].y = fmaf(w.y, v.y, acc[1].y);
        acc[1].z = fmaf(w.y, v.z, acc[1].z);
        acc[1].w = fmaf(w.y, v.w, acc[1].w);
        acc[2].x = fmaf(w.z, v.x, acc[2].x);
        acc[2].y = fmaf(w.z, v.y, acc[2].y);
        acc[2].z = fmaf(w.z, v.z, acc[2].z);
        acc[2].w = fmaf(w.z, v.w, acc[2].w);
        acc[3].x = fmaf(w.w, v.x, acc[3].x);
        acc[3].y = fmaf(w.w, v.y, acc[3].y);
        acc[3].z = fmaf(w.w, v.z, acc[3].z);
        acc[3].w = fmaf(w.w, v.w, acc[3].w);
    }

    // Publish cc-eighth partials: part_s[ty*256 + c*64 + tx].
    #pragma unroll
    for (int c = 0; c < CH_PER_G; c++)
        part_s[ty * 256 + c * 64 + tx] = acc[c];
    __syncthreads();

    // Fold ty 8 -> 4 (1024 float4 folded by 512 threads, 2 each).
    part_s[t]       = f4add(part_s[t],       part_s[t + 1024]);
    part_s[t + 512] = f4add(part_s[t + 512], part_s[t + 1536]);
    __syncthreads();
    // Fold 4 -> 2.
    part_s[t] = f4add(part_s[t], part_s[t + 512]);
    __syncthreads();

    // Final fold 2 -> registers: threads 0..255 own one [c][col] float4 each.
    float4 v0;
    if (t < 256) {
        v0 = f4add(part_s[t], part_s[t + 256]);
        // Slice-local GN partial.
        float ps  = v0.x + v0.y + v0.z + v0.w;
        float pss = fmaf(v0.x, v0.x, fmaf(v0.y, v0.y,
                    fmaf(v0.z, v0.z, v0.w * v0.w)));
        #pragma unroll
        for (int off = 16; off > 0; off >>= 1) {
            ps  += __shfl_xor_sync(0xffffffffu, ps,  off);
            pss += __shfl_xor_sync(0xffffffffu, pss, off);
        }
        const int lane = t & 31, wid = t >> 5;
        if (lane == 0) {
            red_s[wid] = ps;
            red_s[8 + wid] = pss;
        }
    }
    __syncthreads();

    if (t == 0) {
        float ts = 0.f, tss = 0.f;
        #pragma unroll
        for (int w = 0; w < 8; w++) {
            ts  += red_s[w];
            tss += red_s[8 + w];
        }
        // Write own partial locally and into the peer CTA's smem.
        xch[s][0] = ts;
        xch[s][1] = tss;
        const uint32_t local = smem_u32(&xch[s][0]);
        uint32_t remote;
        asm("mapa.shared::cluster.u32 %0, %1, %2;"
            : "=r"(remote) : "r"(local), "r"(s ^ 1));
        asm volatile("st.shared::cluster.f32 [%0], %1;"
                     :: "r"(remote), "f"(ts) : "memory");
        asm volatile("st.shared::cluster.f32 [%0+4], %1;"
                     :: "r"(remote), "f"(tss) : "memory");
    }

    // Cluster barrier: orders the remote stores, makes both partials visible.
    asm volatile("barrier.cluster.arrive.aligned;" ::: "memory");
    asm volatile("barrier.cluster.wait.aligned;"   ::: "memory");

    if (t < 256) {
        // Fixed combine order: slice0 + slice1 -> deterministic.
        const float tot_s  = xch[0][0] + xch[1][0];
        const float tot_ss = xch[0][1] + xch[1][1];
        const float inv_n  = 1.0f / (float)(CH_PER_G * NPT);
        const float m      = tot_s * inv_n;
        const float var    = tot_ss * inv_n - m * m;   // biased (jnp.var)
        const float rst    = rsqrtf(var + EPS_GN);

        const int c   = t >> 6;       // 0..3
        const int col = t & 63;
        const float ga = gamma[c0 + c] * rst;
        const float be = beta[c0 + c];
        float4 y;
        y.x = fmaxf(fmaf(v0.x - m, ga, be), 0.f);
        y.y = fmaxf(fmaf(v0.y - m, ga, be), 0.f);
        y.z = fmaxf(fmaf(v0.z - m, ga, be), 0.f);
        y.w = fmaxf(fmaf(v0.w - m, ga, be), 0.f);
        float4* ob = (float4*)(out + (size_t)b * C_CH * NPT);
        ob[(size_t)(c0 + c) * ROW4 + s * 64 + col] = y;
    }
}

extern "C" void kernel_launch(void* const* d_in, const int* in_sizes, int n_in,
                              void* d_out, int out_size) {
    // metadata order:
    // 0 feat, 1 Wk, 2 bk, 3 Wq, 4 bq, 5 Wv, 6 bv, 7 gn_v_g, 8 gn_v_b,
    // 9 gn1_g, 10 gn1_b, 11 W1, 12 b1, 13 gn2_g, 14 gn2_b, 15 W2, 16 b2
    const float* feat = (const float*)d_in[0];
    const float* Wv   = (const float*)d_in[5];
    const float* bv   = (const float*)d_in[6];
    const float* gn_g = (const float*)d_in[7];
    const float* gn_b = (const float*)d_in[8];
    float* out = (float*)d_out;

    (void)in_sizes; (void)n_in; (void)out_size;

    fused_v_gn_relu_kernel<<<128, NTHREADS>>>(feat, Wv, bv, gn_g, gn_b, out);
}

// round 9
// speedup vs baseline: 1.0150x; 1.0150x over previous
#include <cuda_runtime.h>

// out = relu( GroupNorm32( Wv @ feat + bv, gn_v_g, gn_v_b ) )
// (softmax-weighted sum in the reference is identity: v is constant along the
//  softmax axis and softmax rows sum to 1).
//
// feat [2,128,512], Wv [128,128], out [2,128,512].
// Grid: 64 blocks = B(2) x group(32); one CTA owns a full GN group.
// NO clusters, NO cross-CTA traffic of any kind (A/B vs R5/R7: isolates the
// cluster-barrier + partner-skew cost those shared).
// 512 threads: tx = 128 float4 columns (all 512 pts), ty = 4 cc-quarters.
// Thread: 32 cc x 4 pts x 4 ch = 512 FMA-inst, 32 LDG.128 double-buffered
// in chunks of 8.  Post-loop: 1 smem fold (4 partials) + redundant stats
// from a 32-float smem array -> only 2 syncs after the mainloop.

#define C_CH     128
#define NPT      512
#define CH_PER_G 4
#define EPS_GN   1e-5f
#define NTHREADS 512
#define ROW4     (NPT / 4)     // 128 float4 per feat row
#define CC_PER_T (C_CH / 4)    // 32 cc per ty
#define CHUNK    8
#define NWARPS   (NTHREADS / 32)

__device__ __forceinline__ float4 f4add(float4 a, float4 b) {
    a.x += b.x; a.y += b.y; a.z += b.z; a.w += b.w; return a;
}

__global__ __launch_bounds__(NTHREADS, 1)
void fused_v_gn_relu_kernel(const float* __restrict__ feat,
                            const float* __restrict__ Wv,
                            const float* __restrict__ bv,
                            const float* __restrict__ gamma,
                            const float* __restrict__ beta,
                            float* __restrict__ out) {
    const int g  = blockIdx.x & 31;   // group 0..31
    const int b  = blockIdx.x >> 5;   // batch 0..1
    const int c0 = g * CH_PER_G;
    const int t  = threadIdx.x;       // 0..511
    const int tx = t & 127;           // float4 column (0..127)
    const int ty = t >> 7;            // cc quarter (0..3)

    __shared__ float  wt_s[C_CH * CH_PER_G];          // transposed Wv, 2KB
    __shared__ float4 part_s[4 * CH_PER_G * ROW4];    // [ty][c][col], 32KB
    __shared__ float  red_s[2 * NWARPS];              // warp partials

    // Stage Wv transposed (one element per thread):
    // wt_s[cc*4 + c] = Wv[(c0+c)*128 + cc].
    wt_s[t] = Wv[(c0 + (t & 3)) * C_CH + (t >> 2)];

    // feat as float4 rows; this thread's column within its cc quarter.
    const float4* fp = (const float4*)(feat + (size_t)b * C_CH * NPT)
                       + (size_t)(ty * CC_PER_T) * ROW4 + tx;

    // Prime the double buffer before the sync so LDG latency overlaps it.
    float4 cur[CHUNK], nxt[CHUNK];
    #pragma unroll
    for (int i = 0; i < CHUNK; i++) cur[i] = fp[i * ROW4];

    __syncthreads();

    const float4* wt4 = (const float4*)wt_s;
    const int wbase = ty * CC_PER_T;

    float4 acc[CH_PER_G];
    #pragma unroll
    for (int c = 0; c < CH_PER_G; c++) {
        const float bvc = (ty == 0) ? bv[c0 + c] : 0.f;
        acc[c].x = bvc; acc[c].y = bvc; acc[c].z = bvc; acc[c].w = bvc;
    }

    // Double-buffered mainloop: 4 chunks of (8 LDG.128 + 128 FMA-inst).
    #pragma unroll
    for (int cb = 0; cb < CC_PER_T; cb += CHUNK) {
        if (cb + CHUNK < CC_PER_T) {
            #pragma unroll
            for (int i = 0; i < CHUNK; i++)
                nxt[i] = fp[(cb + CHUNK + i) * ROW4];
        }
        #pragma unroll
        for (int i = 0; i < CHUNK; i++) {
            const float4 w = wt4[wbase + cb + i];   // broadcast LDS.128
            const float4 f = cur[i];
            acc[0].x = fmaf(w.x, f.x, acc[0].x);
            acc[0].y = fmaf(w.x, f.y, acc[0].y);
            acc[0].z = fmaf(w.x, f.z, acc[0].z);
            acc[0].w = fmaf(w.x, f.w, acc[0].w);
            acc[1].x = fmaf(w.y, f.x, acc[1].x);
            acc[1].y = fmaf(w.y, f.y, acc[1].y);
            acc[1].z = fmaf(w.y, f.z, acc[1].z);
            acc[1].w = fmaf(w.y, f.w, acc[1].w);
            acc[2].x = fmaf(w.z, f.x, acc[2].x);
            acc[2].y = fmaf(w.z, f.y, acc[2].y);
            acc[2].z = fmaf(w.z, f.z, acc[2].z);
            acc[2].w = fmaf(w.z, f.w, acc[2].w);
            acc[3].x = fmaf(w.w, f.x, acc[3].x);
            acc[3].y = fmaf(w.w, f.y, acc[3].y);
            acc[3].z = fmaf(w.w, f.z, acc[3].z);
            acc[3].w = fmaf(w.w, f.w, acc[3].w);
        }
        #pragma unroll
        for (int i = 0; i < CHUNK; i++) cur[i] = nxt[i];
    }

    // Publish cc-quarter partials: part_s[ty*512 + c*128 + col].
    #pragma unroll
    for (int c = 0; c < CH_PER_G; c++)
        part_s[ty * 512 + c * ROW4 + tx] = acc[c];
    __syncthreads();

    // Fold 4 partials: thread t owns flat [c][col] index t (c=t>>7, col=t&127).
    float4 v = f4add(f4add(part_s[t], part_s[t + 512]),
                     f4add(part_s[t + 1024], part_s[t + 1536]));

    // Block GN stats: warp shfl reduce -> 16 warp partials -> redundant sum.
    {
        float ps  = v.x + v.y + v.z + v.w;
        float pss = fmaf(v.x, v.x, fmaf(v.y, v.y,
                    fmaf(v.z, v.z, v.w * v.w)));
        #pragma unroll
        for (int off = 16; off > 0; off >>= 1) {
            ps  += __shfl_xor_sync(0xffffffffu, ps,  off);
            pss += __shfl_xor_sync(0xffffffffu, pss, off);
        }
        const int lane = t & 31, wid = t >> 5;
        if (lane == 0) {
            red_s[wid] = ps;
            red_s[NWARPS + wid] = pss;
        }
    }
    __syncthreads();

    // Every thread sums the 16 warp partials redundantly (fixed order).
    float ts = 0.f, tss = 0.f;
    #pragma unroll
    for (int w = 0; w < NWARPS; w++) {
        ts  += red_s[w];
        tss += red_s[NWARPS + w];
    }
    const float inv_n = 1.0f / (float)(CH_PER_G * NPT);
    const float m     = ts * inv_n;
    const float var   = tss * inv_n - m * m;   // biased (jnp.var)
    const float rst   = rsqrtf(var + EPS_GN);

    // Normalize + ReLU + store: one STG.128 per thread.
    {
        const int c   = t >> 7;
        const int col = t & 127;
        const float ga = gamma[c0 + c] * rst;
        const float be = beta[c0 + c];
        float4 y;
        y.x = fmaxf(fmaf(v.x - m, ga, be), 0.f);
        y.y = fmaxf(fmaf(v.y - m, ga, be), 0.f);
        y.z = fmaxf(fmaf(v.z - m, ga, be), 0.f);
        y.w = fmaxf(fmaf(v.w - m, ga, be), 0.f);
        float4* ob = (float4*)(out + (size_t)b * C_CH * NPT);
        ob[(size_t)(c0 + c) * ROW4 + col] = y;
    }
}

extern "C" void kernel_launch(void* const* d_in, const int* in_sizes, int n_in,
                              void* d_out, int out_size) {
    // metadata order:
    // 0 feat, 1 Wk, 2 bk, 3 Wq, 4 bq, 5 Wv, 6 bv, 7 gn_v_g, 8 gn_v_b,
    // 9 gn1_g, 10 gn1_b, 11 W1, 12 b1, 13 gn2_g, 14 gn2_b, 15 W2, 16 b2
    const float* feat = (const float*)d_in[0];
    const float* Wv   = (const float*)d_in[5];
    const float* bv   = (const float*)d_in[6];
    const float* gn_g = (const float*)d_in[7];
    const float* gn_b = (const float*)d_in[8];
    float* out = (float*)d_out;

    (void)in_sizes; (void)n_in; (void)out_size;

    fused_v_gn_relu_kernel<<<64, NTHREADS>>>(feat, Wv, bv, gn_g, gn_b, out);
}